// round 3
// baseline (speedup 1.0000x reference)
#include <cuda_runtime.h>
#include <math.h>

#define N_NODES 50000
#define N_EDGES 800000
#define XD      128
#define HID     128

// Scratch (no cudaMalloc allowed) — device globals.
__device__ float g_esum[(size_t)N_NODES * HID];
__device__ float g_h1[(size_t)N_NODES * HID];
__device__ float g_h2[(size_t)N_NODES * HID];

// ---------------------------------------------------------------------------
// Zero the edge-sum accumulator (must happen every launch; output determinism)
// Exact-fit launch: one float4 store per thread.
// ---------------------------------------------------------------------------
__global__ void zero_kernel(float4* __restrict__ p4) {
    int i = blockIdx.x * blockDim.x + threadIdx.x;
    p4[i] = make_float4(0.f, 0.f, 0.f, 0.f);
}

// ---------------------------------------------------------------------------
// Segment-sum via vector atomics: each thread owns one float4 of one edge row.
// 32 consecutive threads share an edge -> edge_attr reads are 512B coalesced,
// index read is a broadcast, and the 32 lanes hit 32 distinct 16B addresses of
// the destination row (no same-address serialization inside a warp).
// edge_index is int32 (JAX x64 disabled downcasts the requested int64).
// ---------------------------------------------------------------------------
__global__ void scatter_kernel(const float* __restrict__ ea,
                               const int* __restrict__ ei,
                               float* __restrict__ esum) {
    long long tid = (long long)blockIdx.x * blockDim.x + threadIdx.x;
    const long long total = (long long)N_EDGES * 32;
    if (tid >= total) return;
    int e = (int)(tid >> 5);
    int c = (int)(tid & 31);
    int node = ei[e];  // edge_index[0, e]
    if ((unsigned)node >= N_NODES) return;  // defensive: dtype surprises fail softly
    float4 v = reinterpret_cast<const float4*>(ea + (size_t)e * HID)[c];
    float4* dst = reinterpret_cast<float4*>(esum + (size_t)node * HID) + c;
    atomicAdd(dst, v);  // red.global.add.v4.f32 (sm_90+)
}

// ---------------------------------------------------------------------------
// SGEMM: C[M,128] = act(A[M,K] @ B[K,128] + bias), row-major everywhere.
// BM=128, BN=128 (full width), BK=16, 256 threads, 8x8 accumulators/thread.
// CONCAT: K=256 where k<128 reads A, k>=128 reads A2 (fuses the concatenate).
// ELU:    y = x>0 ? x : expm1(x)
// ---------------------------------------------------------------------------
template <bool ELU, bool CONCAT>
__global__ __launch_bounds__(256)
void gemm_kernel(const float* __restrict__ A, const float* __restrict__ A2,
                 const float* __restrict__ B, const float* __restrict__ bias,
                 float* __restrict__ C, int M, int K) {
    const int BM = 128, BN = 128, BK = 16;
    __shared__ float As[BK][BM];      // stored transposed: As[k][m]
    __shared__ float Bs[BK][BN];

    int tid = threadIdx.x;            // 0..255
    int tx = tid & 15;                // col group
    int ty = tid >> 4;                // row group
    int rowBase = blockIdx.x * BM;

    float acc[8][8];
#pragma unroll
    for (int i = 0; i < 8; i++)
#pragma unroll
        for (int j = 0; j < 8; j++) acc[i][j] = 0.f;

    for (int k0 = 0; k0 < K; k0 += BK) {
        const float* Asrc = (CONCAT && k0 >= 128) ? A2 : A;
        int kk0 = (CONCAT && k0 >= 128) ? (k0 - 128) : k0;

        // Load A tile (128 rows x 16 cols) = 512 float4, transpose into As
#pragma unroll
        for (int i = 0; i < 2; i++) {
            int f  = tid + i * 256;
            int r  = f >> 2;          // row within tile
            int c4 = f & 3;           // which float4 of the 16-wide slab
            int row = rowBase + r;
            float4 v = make_float4(0.f, 0.f, 0.f, 0.f);
            if (row < M)
                v = *reinterpret_cast<const float4*>(Asrc + (size_t)row * 128 + kk0 + c4 * 4);
            As[c4 * 4 + 0][r] = v.x;
            As[c4 * 4 + 1][r] = v.y;
            As[c4 * 4 + 2][r] = v.z;
            As[c4 * 4 + 3][r] = v.w;
        }
        // Load B tile (16 rows x 128 cols) = 512 float4
#pragma unroll
        for (int i = 0; i < 2; i++) {
            int f  = tid + i * 256;
            int r  = f >> 5;          // 32 float4 per row
            int c4 = f & 31;
            *reinterpret_cast<float4*>(&Bs[r][c4 * 4]) =
                *reinterpret_cast<const float4*>(B + (size_t)(k0 + r) * 128 + c4 * 4);
        }
        __syncthreads();

#pragma unroll
        for (int k = 0; k < BK; k++) {
            float a[8], b[8];
            *reinterpret_cast<float4*>(a)     = *reinterpret_cast<const float4*>(&As[k][ty * 8]);
            *reinterpret_cast<float4*>(a + 4) = *reinterpret_cast<const float4*>(&As[k][ty * 8 + 4]);
            *reinterpret_cast<float4*>(b)     = *reinterpret_cast<const float4*>(&Bs[k][tx * 8]);
            *reinterpret_cast<float4*>(b + 4) = *reinterpret_cast<const float4*>(&Bs[k][tx * 8 + 4]);
#pragma unroll
            for (int i = 0; i < 8; i++)
#pragma unroll
                for (int j = 0; j < 8; j++) acc[i][j] += a[i] * b[j];
        }
        __syncthreads();
    }

    // Epilogue: bias + optional ELU, float4 stores
    float bv[8];
#pragma unroll
    for (int j = 0; j < 8; j++) bv[j] = bias[tx * 8 + j];

#pragma unroll
    for (int i = 0; i < 8; i++) {
        int row = rowBase + ty * 8 + i;
        if (row >= M) continue;
        float out[8];
#pragma unroll
        for (int j = 0; j < 8; j++) {
            float v = acc[i][j] + bv[j];
            if (ELU) v = (v > 0.f) ? v : expm1f(v);
            out[j] = v;
        }
        float* cp = C + (size_t)row * 128 + tx * 8;
        *reinterpret_cast<float4*>(cp)     = *reinterpret_cast<const float4*>(out);
        *reinterpret_cast<float4*>(cp + 4) = *reinterpret_cast<const float4*>(out + 4);
    }
}

extern "C" void kernel_launch(void* const* d_in, const int* in_sizes, int n_in,
                              void* d_out, int out_size) {
    const float* x    = (const float*)d_in[0];
    const int*   ei   = (const int*)d_in[1];   // [2, E] int32; row 0 = targets
    const float* ea   = (const float*)d_in[2];
    const float* W0   = (const float*)d_in[3];
    const float* b0   = (const float*)d_in[4];
    const float* W2   = (const float*)d_in[5];
    const float* b2   = (const float*)d_in[6];
    const float* W3   = (const float*)d_in[7];
    const float* b3   = (const float*)d_in[8];
    float*       out  = (float*)d_out;

    float *esum, *h1, *h2;
    cudaGetSymbolAddress((void**)&esum, g_esum);
    cudaGetSymbolAddress((void**)&h1, g_h1);
    cudaGetSymbolAddress((void**)&h2, g_h2);

    // 1) zero accumulator: 50000*128/4 = 1.6M float4 = 6250 blocks x 256
    zero_kernel<<<6250, 256>>>(reinterpret_cast<float4*>(esum));

    // 2) segment-sum via float4 atomics
    {
        long long total = (long long)N_EDGES * 32;   // 25.6M threads
        int blocks = (int)((total + 255) / 256);     // 100000 blocks
        scatter_kernel<<<blocks, 256>>>(ea, ei, esum);
    }
    // 3) MLP
    int mblocks = (N_NODES + 127) / 128;  // 391
    gemm_kernel<true,  true ><<<mblocks, 256>>>(x,  esum, W0, b0, h1,  N_NODES, 256);
    gemm_kernel<true,  false><<<mblocks, 256>>>(h1, nullptr, W2, b2, h2, N_NODES, 128);
    gemm_kernel<false, false><<<mblocks, 256>>>(h2, nullptr, W3, b3, out, N_NODES, 128);
}

// round 4
// speedup vs baseline: 1.1273x; 1.1273x over previous
#include <cuda_runtime.h>
#include <math.h>
#include <stdint.h>

#define N_NODES 50000
#define N_EDGES 800000
#define HID     128

// Scratch (no cudaMalloc allowed) — device globals.
__device__ float g_esum[(size_t)N_NODES * HID];
__device__ float g_h1[(size_t)N_NODES * HID];
__device__ float g_h2[(size_t)N_NODES * HID];

// ---------------------------------------------------------------------------
// Zero the edge-sum accumulator. Exact-fit: one float4 per thread.
// ---------------------------------------------------------------------------
__global__ void zero_kernel(float4* __restrict__ p4) {
    int i = blockIdx.x * blockDim.x + threadIdx.x;
    p4[i] = make_float4(0.f, 0.f, 0.f, 0.f);
}

// ---------------------------------------------------------------------------
// Segment-sum via vector atomics (one float4 of one edge row per thread).
// edge_index is int32 (JAX x64 disabled).
// ---------------------------------------------------------------------------
__global__ void scatter_kernel(const float* __restrict__ ea,
                               const int* __restrict__ ei,
                               float* __restrict__ esum) {
    long long tid = (long long)blockIdx.x * blockDim.x + threadIdx.x;
    const long long total = (long long)N_EDGES * 32;
    if (tid >= total) return;
    int e = (int)(tid >> 5);
    int c = (int)(tid & 31);
    int node = ei[e];
    if ((unsigned)node >= N_NODES) return;
    float4 v = reinterpret_cast<const float4*>(ea + (size_t)e * HID)[c];
    float4* dst = reinterpret_cast<float4*>(esum + (size_t)node * HID) + c;
    atomicAdd(dst, v);
}

// ---------------------------------------------------------------------------
// TF32 helpers
// ---------------------------------------------------------------------------
__device__ __forceinline__ uint32_t f2tf32(float f) {
    uint32_t r;
    asm("cvt.rna.tf32.f32 %0, %1;" : "=r"(r) : "f"(f));
    return r;
}
__device__ __forceinline__ void split_tf32(float v, uint32_t& hi, uint32_t& lo) {
    hi = f2tf32(v);
    lo = f2tf32(v - __uint_as_float(hi));
}
__device__ __forceinline__ void mma_tf32(float* c, const uint32_t* a, const uint32_t* b) {
    asm volatile(
        "mma.sync.aligned.m16n8k8.row.col.f32.tf32.tf32.f32 "
        "{%0,%1,%2,%3}, {%4,%5,%6,%7}, {%8,%9}, {%0,%1,%2,%3};"
        : "+f"(c[0]), "+f"(c[1]), "+f"(c[2]), "+f"(c[3])
        : "r"(a[0]), "r"(a[1]), "r"(a[2]), "r"(a[3]), "r"(b[0]), "r"(b[1]));
}

// ---------------------------------------------------------------------------
// TF32x3 tensor-core GEMM: C[M,128] = act(A[M,K] @ B[K,128] + bias).
// BM=128, BN=128, BK=16. 512 threads = 16 warps in 4(M)x4(N); warp tile 32x32.
// 3xTF32: C += Ah*Bh + Al*Bh + Ah*Bl  (residual ~2^-22 — fp32-class accuracy).
// CONCAT: K=256, k<128 from A, k>=128 from A2 (fuses the concatenate).
// ---------------------------------------------------------------------------
#define SPAD 136   // 16-row tiles, 128+8 pad -> conflict-free fragment loads

template <bool ELU_ACT, bool CONCAT>
__global__ __launch_bounds__(512)
void gemm_tf32_kernel(const float* __restrict__ A, const float* __restrict__ A2,
                      const float* __restrict__ B, const float* __restrict__ bias,
                      float* __restrict__ C, int M, int K) {
    __shared__ uint32_t Ah[16][SPAD], Al[16][SPAD];
    __shared__ uint32_t Bh[16][SPAD], Bl[16][SPAD];

    const int tid    = threadIdx.x;
    const int lane   = tid & 31;
    const int wid    = tid >> 5;        // 0..15
    const int warp_m = wid & 3;         // 4 groups x 32 rows
    const int warp_n = wid >> 2;        // 4 groups x 32 cols
    const int gid    = lane >> 2;       // 0..7
    const int tid4   = lane & 3;        // 0..3
    const int rowBase = blockIdx.x * 128;

    float acc[2][4][4];                 // [m_frag][n_frag][reg]
#pragma unroll
    for (int i = 0; i < 2; i++)
#pragma unroll
        for (int j = 0; j < 4; j++)
#pragma unroll
            for (int r = 0; r < 4; r++) acc[i][j][r] = 0.f;

    for (int k0 = 0; k0 < K; k0 += 16) {
        const float* Asrc = (CONCAT && k0 >= 128) ? A2 : A;
        const int kk0 = (CONCAT && k0 >= 128) ? (k0 - 128) : k0;

        // --- Fill A tile (128 x 16): one float4 per thread, split + transpose
        {
            int r  = tid >> 2;          // row in tile
            int c4 = tid & 3;           // float4 slot along k
            int row = rowBase + r;
            float4 v = make_float4(0.f, 0.f, 0.f, 0.f);
            if (row < M)
                v = *reinterpret_cast<const float4*>(Asrc + (size_t)row * 128 + kk0 + c4 * 4);
            uint32_t h, l;
            split_tf32(v.x, h, l); Ah[c4 * 4 + 0][r] = h; Al[c4 * 4 + 0][r] = l;
            split_tf32(v.y, h, l); Ah[c4 * 4 + 1][r] = h; Al[c4 * 4 + 1][r] = l;
            split_tf32(v.z, h, l); Ah[c4 * 4 + 2][r] = h; Al[c4 * 4 + 2][r] = l;
            split_tf32(v.w, h, l); Ah[c4 * 4 + 3][r] = h; Al[c4 * 4 + 3][r] = l;
        }
        // --- Fill B tile (16 x 128): one float4 per thread, split, no transpose
        {
            int r  = tid >> 5;          // 0..15
            int c4 = tid & 31;          // float4 slot along n
            float4 v = *reinterpret_cast<const float4*>(B + (size_t)(k0 + r) * 128 + c4 * 4);
            uint32_t h0,l0,h1,l1,h2,l2,h3,l3;
            split_tf32(v.x, h0, l0); split_tf32(v.y, h1, l1);
            split_tf32(v.z, h2, l2); split_tf32(v.w, h3, l3);
            uint4 hv = make_uint4(h0, h1, h2, h3);
            uint4 lv = make_uint4(l0, l1, l2, l3);
            *reinterpret_cast<uint4*>(&Bh[r][c4 * 4]) = hv;
            *reinterpret_cast<uint4*>(&Bl[r][c4 * 4]) = lv;
        }
        __syncthreads();

#pragma unroll
        for (int ks = 0; ks < 2; ks++) {
            const int kb = ks * 8;
            uint32_t afh[2][4], afl[2][4], bfh[4][2], bfl[4][2];
#pragma unroll
            for (int mi = 0; mi < 2; mi++) {
                int am = warp_m * 32 + mi * 16;
                afh[mi][0] = Ah[kb + tid4    ][am + gid    ];
                afh[mi][1] = Ah[kb + tid4    ][am + gid + 8];
                afh[mi][2] = Ah[kb + tid4 + 4][am + gid    ];
                afh[mi][3] = Ah[kb + tid4 + 4][am + gid + 8];
                afl[mi][0] = Al[kb + tid4    ][am + gid    ];
                afl[mi][1] = Al[kb + tid4    ][am + gid + 8];
                afl[mi][2] = Al[kb + tid4 + 4][am + gid    ];
                afl[mi][3] = Al[kb + tid4 + 4][am + gid + 8];
            }
#pragma unroll
            for (int ni = 0; ni < 4; ni++) {
                int bn = warp_n * 32 + ni * 8;
                bfh[ni][0] = Bh[kb + tid4    ][bn + gid];
                bfh[ni][1] = Bh[kb + tid4 + 4][bn + gid];
                bfl[ni][0] = Bl[kb + tid4    ][bn + gid];
                bfl[ni][1] = Bl[kb + tid4 + 4][bn + gid];
            }
#pragma unroll
            for (int mi = 0; mi < 2; mi++)
#pragma unroll
                for (int ni = 0; ni < 4; ni++) {
                    mma_tf32(acc[mi][ni], afh[mi], bfh[ni]);  // hi*hi
                    mma_tf32(acc[mi][ni], afl[mi], bfh[ni]);  // lo*hi
                    mma_tf32(acc[mi][ni], afh[mi], bfl[ni]);  // hi*lo
                }
        }
        __syncthreads();
    }

    // --- Epilogue: bias + optional ELU, float2 stores
#pragma unroll
    for (int mi = 0; mi < 2; mi++) {
        int row0 = rowBase + warp_m * 32 + mi * 16 + gid;
        int row1 = row0 + 8;
#pragma unroll
        for (int ni = 0; ni < 4; ni++) {
            int col = warp_n * 32 + ni * 8 + tid4 * 2;
            float b0 = bias[col], b1 = bias[col + 1];
            float v0 = acc[mi][ni][0] + b0, v1 = acc[mi][ni][1] + b1;
            float v2 = acc[mi][ni][2] + b0, v3 = acc[mi][ni][3] + b1;
            if (ELU_ACT) {
                v0 = (v0 > 0.f) ? v0 : expm1f(v0);
                v1 = (v1 > 0.f) ? v1 : expm1f(v1);
                v2 = (v2 > 0.f) ? v2 : expm1f(v2);
                v3 = (v3 > 0.f) ? v3 : expm1f(v3);
            }
            if (row0 < M)
                *reinterpret_cast<float2*>(C + (size_t)row0 * 128 + col) = make_float2(v0, v1);
            if (row1 < M)
                *reinterpret_cast<float2*>(C + (size_t)row1 * 128 + col) = make_float2(v2, v3);
        }
    }
}

extern "C" void kernel_launch(void* const* d_in, const int* in_sizes, int n_in,
                              void* d_out, int out_size) {
    const float* x    = (const float*)d_in[0];
    const int*   ei   = (const int*)d_in[1];   // [2, E] int32; row 0 = targets
    const float* ea   = (const float*)d_in[2];
    const float* W0   = (const float*)d_in[3];
    const float* b0   = (const float*)d_in[4];
    const float* W2   = (const float*)d_in[5];
    const float* b2   = (const float*)d_in[6];
    const float* W3   = (const float*)d_in[7];
    const float* b3   = (const float*)d_in[8];
    float*       out  = (float*)d_out;

    float *esum, *h1, *h2;
    cudaGetSymbolAddress((void**)&esum, g_esum);
    cudaGetSymbolAddress((void**)&h1, g_h1);
    cudaGetSymbolAddress((void**)&h2, g_h2);

    // 1) zero accumulator: 50000*128/4 = 1.6M float4 = 6250 blocks x 256
    zero_kernel<<<6250, 256>>>(reinterpret_cast<float4*>(esum));

    // 2) segment-sum via float4 atomics
    {
        long long total = (long long)N_EDGES * 32;   // 25.6M threads
        int blocks = (int)((total + 255) / 256);     // 100000 blocks
        scatter_kernel<<<blocks, 256>>>(ea, ei, esum);
    }
    // 3) MLP on tensor cores (TF32x3)
    int mblocks = (N_NODES + 127) / 128;  // 391
    gemm_tf32_kernel<true,  true ><<<mblocks, 512>>>(x,  esum,    W0, b0, h1,  N_NODES, 256);
    gemm_tf32_kernel<true,  false><<<mblocks, 512>>>(h1, nullptr, W2, b2, h2,  N_NODES, 128);
    gemm_tf32_kernel<false, false><<<mblocks, 512>>>(h2, nullptr, W3, b3, out, N_NODES, 128);
}

// round 5
// speedup vs baseline: 1.2231x; 1.0850x over previous
#include <cuda_runtime.h>
#include <math.h>
#include <stdint.h>

#define N_NODES 50000
#define N_EDGES 800000
#define HID     128

// Scratch (no cudaMalloc allowed) — device globals.
__device__ float g_esum[(size_t)N_NODES * HID];
__device__ float g_h1[(size_t)N_NODES * HID];
__device__ float g_h2[(size_t)N_NODES * HID];

// ---------------------------------------------------------------------------
// Zero the edge-sum accumulator. Exact-fit: one float4 per thread.
// ---------------------------------------------------------------------------
__global__ void zero_kernel(float4* __restrict__ p4) {
    int i = blockIdx.x * blockDim.x + threadIdx.x;
    p4[i] = make_float4(0.f, 0.f, 0.f, 0.f);
}

// ---------------------------------------------------------------------------
// Segment-sum via vector atomics. One warp per edge; lane c owns one float4.
// edge_index is int32 (JAX x64 disabled).
// ---------------------------------------------------------------------------
__global__ void scatter_kernel(const float* __restrict__ ea,
                               const int* __restrict__ ei,
                               float* __restrict__ esum) {
    long long tid = (long long)blockIdx.x * blockDim.x + threadIdx.x;
    const long long total = (long long)N_EDGES * 32;
    if (tid >= total) return;
    int e = (int)(tid >> 5);
    int c = (int)(tid & 31);
    int node = ei[e];
    if ((unsigned)node >= N_NODES) return;
    float4 v = reinterpret_cast<const float4*>(ea + (size_t)e * HID)[c];
    float4* dst = reinterpret_cast<float4*>(esum + (size_t)node * HID) + c;
    atomicAdd(dst, v);
}

// ---------------------------------------------------------------------------
// TF32 helpers
// ---------------------------------------------------------------------------
__device__ __forceinline__ uint32_t f2tf32(float f) {
    uint32_t r;
    asm("cvt.rna.tf32.f32 %0, %1;" : "=r"(r) : "f"(f));
    return r;
}
__device__ __forceinline__ void split_tf32(float v, uint32_t& hi, uint32_t& lo) {
    hi = f2tf32(v);
    lo = f2tf32(v - __uint_as_float(hi));
}
__device__ __forceinline__ void mma_tf32(float* c, const uint32_t* a, const uint32_t* b) {
    asm volatile(
        "mma.sync.aligned.m16n8k8.row.col.f32.tf32.tf32.f32 "
        "{%0,%1,%2,%3}, {%4,%5,%6,%7}, {%8,%9}, {%0,%1,%2,%3};"
        : "+f"(c[0]), "+f"(c[1]), "+f"(c[2]), "+f"(c[3])
        : "r"(a[0]), "r"(a[1]), "r"(a[2]), "r"(a[3]), "r"(b[0]), "r"(b[1]));
}

// ---------------------------------------------------------------------------
// TF32x3 tensor-core GEMM, 2-stage double buffered.
// C[M,128] = act(A[M,K] @ B[K,128] + bias). BM=BN=128, BK=16, 512 threads.
// 16 warps in 4(M)x4(N); warp tile 32x32.
// Pipeline per k-tile: issue LDG(t+1) -> compute(t) from smem -> split+STS(t+1)
// into the alternate buffer -> one __syncthreads.
// ---------------------------------------------------------------------------
#define SPAD 136

template <bool ELU_ACT, bool CONCAT>
__global__ __launch_bounds__(512)
void gemm_tf32_kernel(const float* __restrict__ A, const float* __restrict__ A2,
                      const float* __restrict__ B, const float* __restrict__ bias,
                      float* __restrict__ C, int M, int K) {
    __shared__ uint32_t Ah[2][16][SPAD], Al[2][16][SPAD];
    __shared__ uint32_t Bh[2][16][SPAD], Bl[2][16][SPAD];

    const int tid    = threadIdx.x;
    const int lane   = tid & 31;
    const int wid    = tid >> 5;
    const int warp_m = wid & 3;
    const int warp_n = wid >> 2;
    const int gid    = lane >> 2;       // 0..7
    const int tid4   = lane & 3;        // 0..3
    const int rowBase = blockIdx.x * 128;

    // Per-thread load coordinates
    const int ar  = tid >> 2;           // A: row in tile (0..127)
    const int ac4 = tid & 3;            // A: float4 slot along k (0..3)
    const int arow = rowBase + ar;
    const int br  = tid >> 5;           // B: k-row in tile (0..15)
    const int bc4 = tid & 31;           // B: float4 slot along n (0..31)

    const int nIter = K >> 4;

    float acc[2][4][4];
#pragma unroll
    for (int i = 0; i < 2; i++)
#pragma unroll
        for (int j = 0; j < 4; j++)
#pragma unroll
            for (int r = 0; r < 4; r++) acc[i][j][r] = 0.f;

    // ---- tile loaders ----
    auto loadA = [&](int t) -> float4 {
        int kk = t * 16;
        const float* src = (CONCAT && kk >= 128) ? A2 : A;
        int kbase = (CONCAT && kk >= 128) ? (kk - 128) : kk;
        float4 v = make_float4(0.f, 0.f, 0.f, 0.f);
        if (arow < M)
            v = *reinterpret_cast<const float4*>(src + (size_t)arow * 128 + kbase + ac4 * 4);
        return v;
    };
    auto loadB = [&](int t) -> float4 {
        return *reinterpret_cast<const float4*>(B + (size_t)(t * 16 + br) * 128 + bc4 * 4);
    };
    auto storeSplit = [&](int buf, float4 av, float4 bv) {
        uint32_t h, l;
        split_tf32(av.x, h, l); Ah[buf][ac4 * 4 + 0][ar] = h; Al[buf][ac4 * 4 + 0][ar] = l;
        split_tf32(av.y, h, l); Ah[buf][ac4 * 4 + 1][ar] = h; Al[buf][ac4 * 4 + 1][ar] = l;
        split_tf32(av.z, h, l); Ah[buf][ac4 * 4 + 2][ar] = h; Al[buf][ac4 * 4 + 2][ar] = l;
        split_tf32(av.w, h, l); Ah[buf][ac4 * 4 + 3][ar] = h; Al[buf][ac4 * 4 + 3][ar] = l;
        uint32_t h0,l0,h1,l1,h2,l2,h3,l3;
        split_tf32(bv.x, h0, l0); split_tf32(bv.y, h1, l1);
        split_tf32(bv.z, h2, l2); split_tf32(bv.w, h3, l3);
        *reinterpret_cast<uint4*>(&Bh[buf][br][bc4 * 4]) = make_uint4(h0, h1, h2, h3);
        *reinterpret_cast<uint4*>(&Bl[buf][br][bc4 * 4]) = make_uint4(l0, l1, l2, l3);
    };
    auto compute = [&](int buf) {
#pragma unroll
        for (int ks = 0; ks < 2; ks++) {
            const int kb = ks * 8;
            uint32_t afh[2][4], afl[2][4], bfh[4][2], bfl[4][2];
#pragma unroll
            for (int mi = 0; mi < 2; mi++) {
                int am = warp_m * 32 + mi * 16;
                afh[mi][0] = Ah[buf][kb + tid4    ][am + gid    ];
                afh[mi][1] = Ah[buf][kb + tid4    ][am + gid + 8];
                afh[mi][2] = Ah[buf][kb + tid4 + 4][am + gid    ];
                afh[mi][3] = Ah[buf][kb + tid4 + 4][am + gid + 8];
                afl[mi][0] = Al[buf][kb + tid4    ][am + gid    ];
                afl[mi][1] = Al[buf][kb + tid4    ][am + gid + 8];
                afl[mi][2] = Al[buf][kb + tid4 + 4][am + gid    ];
                afl[mi][3] = Al[buf][kb + tid4 + 4][am + gid + 8];
            }
#pragma unroll
            for (int ni = 0; ni < 4; ni++) {
                int bn = warp_n * 32 + ni * 8;
                bfh[ni][0] = Bh[buf][kb + tid4    ][bn + gid];
                bfh[ni][1] = Bh[buf][kb + tid4 + 4][bn + gid];
                bfl[ni][0] = Bl[buf][kb + tid4    ][bn + gid];
                bfl[ni][1] = Bl[buf][kb + tid4 + 4][bn + gid];
            }
#pragma unroll
            for (int mi = 0; mi < 2; mi++)
#pragma unroll
                for (int ni = 0; ni < 4; ni++) {
                    mma_tf32(acc[mi][ni], afh[mi], bfh[ni]);  // hi*hi
                    mma_tf32(acc[mi][ni], afl[mi], bfh[ni]);  // lo*hi
                    mma_tf32(acc[mi][ni], afh[mi], bfl[ni]);  // hi*lo
                }
        }
    };

    // ---- pipelined mainloop ----
    {
        float4 av = loadA(0), bv = loadB(0);
        storeSplit(0, av, bv);
    }
    __syncthreads();
    int buf = 0;
    for (int t = 0; t < nIter; t++) {
        float4 av, bv;
        const bool more = (t + 1 < nIter);
        if (more) { av = loadA(t + 1); bv = loadB(t + 1); }  // LDGs in flight
        compute(buf);                                        // covers LDG latency
        if (more) {
            storeSplit(buf ^ 1, av, bv);
            __syncthreads();
            buf ^= 1;
        }
    }

    // ---- epilogue: bias + optional ELU, float2 stores ----
#pragma unroll
    for (int mi = 0; mi < 2; mi++) {
        int row0 = rowBase + warp_m * 32 + mi * 16 + gid;
        int row1 = row0 + 8;
#pragma unroll
        for (int ni = 0; ni < 4; ni++) {
            int col = warp_n * 32 + ni * 8 + tid4 * 2;
            float b0 = bias[col], b1 = bias[col + 1];
            float v0 = acc[mi][ni][0] + b0, v1 = acc[mi][ni][1] + b1;
            float v2 = acc[mi][ni][2] + b0, v3 = acc[mi][ni][3] + b1;
            if (ELU_ACT) {
                v0 = (v0 > 0.f) ? v0 : expm1f(v0);
                v1 = (v1 > 0.f) ? v1 : expm1f(v1);
                v2 = (v2 > 0.f) ? v2 : expm1f(v2);
                v3 = (v3 > 0.f) ? v3 : expm1f(v3);
            }
            if (row0 < M)
                *reinterpret_cast<float2*>(C + (size_t)row0 * 128 + col) = make_float2(v0, v1);
            if (row1 < M)
                *reinterpret_cast<float2*>(C + (size_t)row1 * 128 + col) = make_float2(v2, v3);
        }
    }
}

extern "C" void kernel_launch(void* const* d_in, const int* in_sizes, int n_in,
                              void* d_out, int out_size) {
    const float* x    = (const float*)d_in[0];
    const int*   ei   = (const int*)d_in[1];   // [2, E] int32; row 0 = targets
    const float* ea   = (const float*)d_in[2];
    const float* W0   = (const float*)d_in[3];
    const float* b0   = (const float*)d_in[4];
    const float* W2   = (const float*)d_in[5];
    const float* b2   = (const float*)d_in[6];
    const float* W3   = (const float*)d_in[7];
    const float* b3   = (const float*)d_in[8];
    float*       out  = (float*)d_out;

    float *esum, *h1, *h2;
    cudaGetSymbolAddress((void**)&esum, g_esum);
    cudaGetSymbolAddress((void**)&h1, g_h1);
    cudaGetSymbolAddress((void**)&h2, g_h2);

    // 1) zero accumulator: 50000*128/4 = 1.6M float4 = 6250 blocks x 256
    zero_kernel<<<6250, 256>>>(reinterpret_cast<float4*>(esum));

    // 2) segment-sum via float4 atomics
    {
        long long total = (long long)N_EDGES * 32;   // 25.6M threads
        int blocks = (int)((total + 255) / 256);     // 100000 blocks
        scatter_kernel<<<blocks, 256>>>(ea, ei, esum);
    }
    // 3) MLP on tensor cores (TF32x3, double buffered)
    int mblocks = (N_NODES + 127) / 128;  // 391
    gemm_tf32_kernel<true,  true ><<<mblocks, 512>>>(x,  esum,    W0, b0, h1,  N_NODES, 256);
    gemm_tf32_kernel<true,  false><<<mblocks, 512>>>(h1, nullptr, W2, b2, h2,  N_NODES, 128);
    gemm_tf32_kernel<false, false><<<mblocks, 512>>>(h2, nullptr, W3, b3, out, N_NODES, 128);
}